// round 7
// baseline (speedup 1.0000x reference)
#include <cuda_runtime.h>

#define NUM_NODES  100000
#define MAX_EDGES  1700000
#define NUM_GRAPHS 512
#define F1 128
#define F2 64
#define BN_EPS 1e-5f

// ---------------- scratch (static device globals; no allocation) ----------------
__device__ __align__(16) int   g_cnt [NUM_NODES];     // edge count per dst
__device__ __align__(16) int   g_off [NUM_NODES];     // CSR start
__device__ __align__(16) int   g_cur [NUM_NODES];     // fill cursor
__device__ __align__(16) int   g_esrc[MAX_EDGES];     // src ids grouped by dst
__device__ __align__(16) float g_dis [NUM_NODES];
__device__ __align__(16) float g_xw1 [NUM_NODES * F1];  // pre-scaled by dis[row]
__device__ __align__(16) float g_acc1[NUM_NODES * F1];
__device__ __align__(16) float g_xw2 [NUM_NODES * F2];  // pre-scaled by dis[row]
__device__ __align__(16) float g_pooled[NUM_GRAPHS * F2];
__device__ __align__(16) float g_mean[F2];
__device__ __align__(16) float g_rstd[F2];

__device__ __forceinline__ void red_add_v2(float* p, float x, float y) {
    asm volatile("red.global.add.v2.f32 [%0], {%1,%2};"
                 :: "l"(p), "f"(x), "f"(y) : "memory");
}

// ---------------- CSR build ----------------
__global__ void k_count(const int* __restrict__ dst, int E) {
    int e = blockIdx.x * blockDim.x + threadIdx.x;
    if (e < E) atomicAdd(&g_cnt[dst[e]], 1);
}

// single block, 1024 threads: exclusive scan of g_cnt -> g_off/g_cur, dis = rsqrt(cnt+1)
__global__ void k_scan(int n) {
    __shared__ int partial[1024];
    int tid = threadIdx.x;
    int ch  = (n + 1023) / 1024;
    int base = tid * ch;
    int sum = 0;
    for (int i = 0; i < ch; i++) {
        int idx = base + i;
        if (idx < n) sum += g_cnt[idx];
    }
    partial[tid] = sum;
    __syncthreads();
#pragma unroll
    for (int off = 1; off < 1024; off <<= 1) {
        int add = (tid >= off) ? partial[tid - off] : 0;
        __syncthreads();
        partial[tid] += add;
        __syncthreads();
    }
    int run = (tid > 0) ? partial[tid - 1] : 0;
    for (int i = 0; i < ch; i++) {
        int idx = base + i;
        if (idx < n) {
            int c = g_cnt[idx];
            g_off[idx] = run;
            g_cur[idx] = run;
            g_dis[idx] = rsqrtf((float)(c + 1));   // +1 self-loop
            run += c;
        }
    }
}

__global__ void k_fill(const int* __restrict__ src, const int* __restrict__ dst, int E) {
    int e = blockIdx.x * blockDim.x + threadIdx.x;
    if (e < E) {
        int slot = atomicAdd(&g_cur[dst[e]], 1);
        g_esrc[slot] = src[e];
    }
}

// -------- GEMM 1: xw1' = (x @ W1) * dis[row]   [N,128]x[128,128] -----------
__global__ void k_gemm1(const float* __restrict__ x, const float* __restrict__ W, int n) {
    __shared__ float xs[64 * 128];
    int row0 = blockIdx.x * 64;
    int tid  = threadIdx.x;

    const float4* x4  = (const float4*)x;
    float4*       xs4 = (float4*)xs;
#pragma unroll
    for (int i = 0; i < 8; i++) {
        int idx = tid + i * 256;
        int r   = idx >> 5;
        int row = row0 + r;
        xs4[idx] = (row < n) ? __ldcs(&x4[(size_t)row * 32 + (idx & 31)])   // streaming: no reuse
                             : make_float4(0.f, 0.f, 0.f, 0.f);
    }
    __syncthreads();

    int colg  = tid & 31;
    int rbase = (tid >> 5) * 8;
    float4 acc[8];
#pragma unroll
    for (int i = 0; i < 8; i++) acc[i] = make_float4(0.f, 0.f, 0.f, 0.f);

    const float4* W4 = (const float4*)W;
    for (int k = 0; k < 128; k++) {
        float4 w = __ldg(&W4[k * 32 + colg]);
#pragma unroll
        for (int i = 0; i < 8; i++) {
            float a = xs[(rbase + i) * 128 + k];
            acc[i].x += a * w.x; acc[i].y += a * w.y;
            acc[i].z += a * w.z; acc[i].w += a * w.w;
        }
    }
#pragma unroll
    for (int i = 0; i < 8; i++) {
        int row = row0 + rbase + i;
        if (row < n) {
            float s = g_dis[row];
            float4 v = acc[i];
            v.x *= s; v.y *= s; v.z *= s; v.w *= s;
            ((float4*)g_xw1)[(size_t)row * 32 + colg] = v;   // keep resident in L2
        }
    }
}

// ---- gather 1: acc1[d] = dis[d] * (xw1'[d] + sum_{s in N(d)} xw1'[s]) ------
__global__ void k_gather1(int n) {
    int d    = (blockIdx.x * blockDim.x + threadIdx.x) >> 5;
    int lane = threadIdx.x & 31;
    if (d >= n) return;
    int beg = g_off[d];
    int cnt = g_cnt[d];
    float dd = g_dis[d];

    float4 acc = __ldg(&((const float4*)(g_xw1 + (size_t)d * 128))[lane]);

    const int* es = g_esrc + beg;
    int i = 0;
    for (; i + 4 <= cnt; i += 4) {
        int s0 = __ldg(&es[i + 0]);
        int s1 = __ldg(&es[i + 1]);
        int s2 = __ldg(&es[i + 2]);
        int s3 = __ldg(&es[i + 3]);
        float4 u0 = __ldg(&((const float4*)(g_xw1 + (size_t)s0 * 128))[lane]);
        float4 u1 = __ldg(&((const float4*)(g_xw1 + (size_t)s1 * 128))[lane]);
        float4 u2 = __ldg(&((const float4*)(g_xw1 + (size_t)s2 * 128))[lane]);
        float4 u3 = __ldg(&((const float4*)(g_xw1 + (size_t)s3 * 128))[lane]);
        acc.x += u0.x + u1.x + u2.x + u3.x;
        acc.y += u0.y + u1.y + u2.y + u3.y;
        acc.z += u0.z + u1.z + u2.z + u3.z;
        acc.w += u0.w + u1.w + u2.w + u3.w;
    }
    for (; i < cnt; i++) {
        int s = __ldg(&es[i]);
        float4 u = __ldg(&((const float4*)(g_xw1 + (size_t)s * 128))[lane]);
        acc.x += u.x; acc.y += u.y; acc.z += u.z; acc.w += u.w;
    }
    acc.x *= dd; acc.y *= dd; acc.z *= dd; acc.w *= dd;
    __stcs(&((float4*)(g_acc1 + (size_t)d * 128))[lane], acc);   // streaming store: protect xw1 residency
}

// ---- GEMM 2: xw2' = (relu(acc1+b1) @ W2) * dis[row]  [N,128]x[128,64] -----
__global__ void k_gemm2(const float* __restrict__ W2, const float* __restrict__ b1, int n) {
    __shared__ float hs[64 * 128];
    __shared__ float b1s[128];
    int row0 = blockIdx.x * 64;
    int tid  = threadIdx.x;
    if (tid < 128) b1s[tid] = b1[tid];
    __syncthreads();

    const float4* a4  = (const float4*)g_acc1;
    float4*       hs4 = (float4*)hs;
#pragma unroll
    for (int i = 0; i < 8; i++) {
        int idx = tid + i * 256;
        int r   = idx >> 5;
        int k4  = idx & 31;
        int row = row0 + r;
        float4 v = (row < n) ? __ldcs(&a4[(size_t)row * 32 + k4])   // last use of acc1
                             : make_float4(0.f, 0.f, 0.f, 0.f);
        v.x = fmaxf(v.x + b1s[k4 * 4 + 0], 0.f);
        v.y = fmaxf(v.y + b1s[k4 * 4 + 1], 0.f);
        v.z = fmaxf(v.z + b1s[k4 * 4 + 2], 0.f);
        v.w = fmaxf(v.w + b1s[k4 * 4 + 3], 0.f);
        hs4[idx] = v;
    }
    __syncthreads();

    int colg  = tid & 15;
    int rbase = (tid >> 4) * 4;
    float4 acc[4];
#pragma unroll
    for (int i = 0; i < 4; i++) acc[i] = make_float4(0.f, 0.f, 0.f, 0.f);

    const float4* W4 = (const float4*)W2;
    for (int k = 0; k < 128; k++) {
        float4 w = __ldg(&W4[k * 16 + colg]);
#pragma unroll
        for (int i = 0; i < 4; i++) {
            float a = hs[(rbase + i) * 128 + k];
            acc[i].x += a * w.x; acc[i].y += a * w.y;
            acc[i].z += a * w.z; acc[i].w += a * w.w;
        }
    }
#pragma unroll
    for (int i = 0; i < 4; i++) {
        int row = row0 + rbase + i;
        if (row < n) {
            float s = g_dis[row];
            float4 v = acc[i];
            v.x *= s; v.y *= s; v.z *= s; v.w *= s;
            ((float4*)g_xw2)[(size_t)row * 16 + colg] = v;   // keep resident
        }
    }
}

// ---- gather 2 + pool: pooled[batch[d]] += relu(dd*(self+sum) + b2) --------
__global__ void k_gather2(const int* __restrict__ batch, const float* __restrict__ b2, int n) {
    int d    = (blockIdx.x * blockDim.x + threadIdx.x) >> 5;
    int lane = threadIdx.x & 31;
    if (d >= n) return;
    int beg = g_off[d];
    int cnt = g_cnt[d];
    float dd = g_dis[d];

    float2 acc = __ldg(&((const float2*)(g_xw2 + (size_t)d * 64))[lane]);

    const int* es = g_esrc + beg;
    int i = 0;
    for (; i + 4 <= cnt; i += 4) {
        int s0 = __ldg(&es[i + 0]);
        int s1 = __ldg(&es[i + 1]);
        int s2 = __ldg(&es[i + 2]);
        int s3 = __ldg(&es[i + 3]);
        float2 u0 = __ldg(&((const float2*)(g_xw2 + (size_t)s0 * 64))[lane]);
        float2 u1 = __ldg(&((const float2*)(g_xw2 + (size_t)s1 * 64))[lane]);
        float2 u2 = __ldg(&((const float2*)(g_xw2 + (size_t)s2 * 64))[lane]);
        float2 u3 = __ldg(&((const float2*)(g_xw2 + (size_t)s3 * 64))[lane]);
        acc.x += u0.x + u1.x + u2.x + u3.x;
        acc.y += u0.y + u1.y + u2.y + u3.y;
    }
    for (; i < cnt; i++) {
        int s = __ldg(&es[i]);
        float2 u = __ldg(&((const float2*)(g_xw2 + (size_t)s * 64))[lane]);
        acc.x += u.x; acc.y += u.y;
    }
    float2 b = __ldg(&((const float2*)b2)[lane]);
    float a0 = fmaxf(acc.x * dd + b.x, 0.f);
    float a1 = fmaxf(acc.y * dd + b.y, 0.f);
    int g = __ldg(&batch[d]);
    red_add_v2(&g_pooled[g * 64 + lane * 2], a0, a1);
}

// ---------------- BN statistics: 256 threads = 64 feat x 4 groups ----------
__global__ void k_bnstats() {
    __shared__ float ssum[256], ssq[256];
    int f   = threadIdx.x & 63;
    int grp = threadIdx.x >> 6;     // 0..3
    float s = 0.f, q = 0.f;
    for (int g = grp; g < NUM_GRAPHS; g += 4) {
        float v = g_pooled[g * 64 + f];
        s += v; q += v * v;
    }
    ssum[threadIdx.x] = s; ssq[threadIdx.x] = q;
    __syncthreads();
    if (grp == 0) {
        s = ssum[f] + ssum[f + 64] + ssum[f + 128] + ssum[f + 192];
        q = ssq [f] + ssq [f + 64] + ssq [f + 128] + ssq [f + 192];
        float m   = s * (1.0f / NUM_GRAPHS);
        float var = q * (1.0f / NUM_GRAPHS) - m * m;
        g_mean[f] = m;
        g_rstd[f] = rsqrtf(var + BN_EPS);
    }
}

// ---------------- head: BN affine + MLP; write (out, h) --------------------
__global__ void k_head(const float* __restrict__ gamma, const float* __restrict__ beta,
                       const float* __restrict__ Wo1,   const float* __restrict__ bo1,
                       const float* __restrict__ Wo2,   const float* __restrict__ bo2,
                       float* __restrict__ out) {
    int g = blockIdx.x * blockDim.x + threadIdx.x;
    if (g >= NUM_GRAPHS) return;
    float hid[24];
#pragma unroll
    for (int j = 0; j < 24; j++) hid[j] = __ldg(&bo1[j]);

    float* hout = out + NUM_GRAPHS + (size_t)g * 64;   // h = pooled (stop_gradient)
    for (int f = 0; f < 64; f++) {
        float p = g_pooled[g * 64 + f];
        hout[f] = p;
        float xn = (p - g_mean[f]) * g_rstd[f] * __ldg(&gamma[f]) + __ldg(&beta[f]);
#pragma unroll
        for (int j = 0; j < 24; j++)
            hid[j] += xn * __ldg(&Wo1[f * 24 + j]);
    }
    float o = __ldg(&bo2[0]);
#pragma unroll
    for (int j = 0; j < 24; j++)
        o += fmaxf(hid[j], 0.f) * __ldg(&Wo2[j]);
    out[g] = o;
}

// ---------------- launch ----------------
extern "C" void kernel_launch(void* const* d_in, const int* in_sizes, int n_in,
                              void* d_out, int out_size) {
    const float* x     = (const float*)d_in[0];
    const int*   ei    = (const int*)d_in[1];
    const int*   batch = (const int*)d_in[2];
    const float* W1    = (const float*)d_in[3];
    const float* b1    = (const float*)d_in[4];
    const float* W2    = (const float*)d_in[5];
    const float* b2    = (const float*)d_in[6];
    const float* gamma = (const float*)d_in[7];
    const float* beta  = (const float*)d_in[8];
    const float* Wo1   = (const float*)d_in[9];
    const float* bo1   = (const float*)d_in[10];
    const float* Wo2   = (const float*)d_in[11];
    const float* bo2   = (const float*)d_in[12];

    int N = in_sizes[0] / F1;
    int E = in_sizes[1] / 2;
    const int* src = ei;
    const int* dst = ei + E;
    float* out = (float*)d_out;

    void* cnt_ptr = nullptr;
    void* pooled_ptr = nullptr;
    cudaGetSymbolAddress(&cnt_ptr, g_cnt);
    cudaGetSymbolAddress(&pooled_ptr, g_pooled);
    cudaMemsetAsync(cnt_ptr, 0, NUM_NODES * sizeof(int));
    cudaMemsetAsync(pooled_ptr, 0, NUM_GRAPHS * F2 * sizeof(float));

    k_count<<<(E + 255) / 256, 256>>>(dst, E);
    k_scan <<<1, 1024>>>(N);
    k_fill <<<(E + 255) / 256, 256>>>(src, dst, E);

    k_gemm1  <<<(N + 63) / 64, 256>>>(x, W1, N);
    k_gather1<<<(N + 7) / 8, 256>>>(N);

    k_gemm2  <<<(N + 63) / 64, 256>>>(W2, b1, N);
    k_gather2<<<(N + 7) / 8, 256>>>(batch, b2, N);

    k_bnstats<<<1, 256>>>();
    k_head<<<(NUM_GRAPHS + 127) / 128, 128>>>(gamma, beta, Wo1, bo1, Wo2, bo2, out);
}

// round 8
// speedup vs baseline: 1.5330x; 1.5330x over previous
#include <cuda_runtime.h>

#define NUM_NODES  100000
#define NUM_GRAPHS 512
#define CAP 96                 // max in-degree slots (Poisson(16) tail: overflow ~1e-20)
#define F1 128
#define F2 64
#define BN_EPS 1e-5f

// ---------------- scratch (static device globals; no allocation) ----------------
__device__ __align__(16) int   g_cnt [NUM_NODES];          // in-degree (excl self)
__device__ __align__(16) int   g_esrc[NUM_NODES * CAP];    // bucket CSR: src ids per dst
__device__ __align__(16) float g_dis [NUM_NODES];
__device__ __align__(16) float g_xw1 [NUM_NODES * F1];     // pre-scaled by dis[row]
__device__ __align__(16) float g_acc1[NUM_NODES * F1];
__device__ __align__(16) float g_xw2 [NUM_NODES * F2];     // pre-scaled by dis[row]
__device__ __align__(16) float g_pooled[NUM_GRAPHS * F2];
__device__ __align__(16) float g_mean[F2];
__device__ __align__(16) float g_rstd[F2];

__device__ __forceinline__ void red_add_v2(float* p, float x, float y) {
    asm volatile("red.global.add.v2.f32 [%0], {%1,%2};"
                 :: "l"(p), "f"(x), "f"(y) : "memory");
}

// ---------------- fused count + bucket fill (kernel 0) ----------------
__global__ void k_fill2(const int* __restrict__ src, const int* __restrict__ dst, int E) {
    int e = blockIdx.x * blockDim.x + threadIdx.x;
    if (e < E) {
        int d = dst[e];
        int slot = atomicAdd(&g_cnt[d], 1);
        if (slot < CAP) g_esrc[(size_t)d * CAP + slot] = src[e];
    }
}

// ---------------- dis = rsqrt(deg+1) (kernel 1) ----------------
__global__ void k_dis(int n) {
    int i = blockIdx.x * blockDim.x + threadIdx.x;
    if (i < n) g_dis[i] = rsqrtf((float)(g_cnt[i] + 1));
}

// -------- GEMM 1 (kernel 2): xw1' = (x @ W1) * dis[row]  [N,128]x[128,128] --
__global__ void k_gemm1(const float* __restrict__ x, const float* __restrict__ W, int n) {
    __shared__ float xs[64 * 128];
    int row0 = blockIdx.x * 64;
    int tid  = threadIdx.x;

    const float4* x4  = (const float4*)x;
    float4*       xs4 = (float4*)xs;
#pragma unroll
    for (int i = 0; i < 8; i++) {
        int idx = tid + i * 256;
        int r   = idx >> 5;
        int row = row0 + r;
        xs4[idx] = (row < n) ? __ldcs(&x4[(size_t)row * 32 + (idx & 31)])
                             : make_float4(0.f, 0.f, 0.f, 0.f);
    }
    __syncthreads();

    int colg  = tid & 31;
    int rbase = (tid >> 5) * 8;
    float4 acc[8];
#pragma unroll
    for (int i = 0; i < 8; i++) acc[i] = make_float4(0.f, 0.f, 0.f, 0.f);

    const float4* W4 = (const float4*)W;
    for (int k = 0; k < 128; k += 2) {
        float4 w0 = __ldg(&W4[k * 32 + colg]);
        float4 w1 = __ldg(&W4[(k + 1) * 32 + colg]);
#pragma unroll
        for (int i = 0; i < 8; i++) {
            float2 a = *(const float2*)&xs[(rbase + i) * 128 + k];   // LDS.64
            acc[i].x += a.x * w0.x + a.y * w1.x;
            acc[i].y += a.x * w0.y + a.y * w1.y;
            acc[i].z += a.x * w0.z + a.y * w1.z;
            acc[i].w += a.x * w0.w + a.y * w1.w;
        }
    }
#pragma unroll
    for (int i = 0; i < 8; i++) {
        int row = row0 + rbase + i;
        if (row < n) {
            float s = g_dis[row];
            float4 v = acc[i];
            v.x *= s; v.y *= s; v.z *= s; v.w *= s;
            ((float4*)g_xw1)[(size_t)row * 32 + colg] = v;
        }
    }
}

// ---- gather 1 (kernel 3): acc1[d] = dis[d]*(xw1'[d] + sum xw1'[s]) --------
// 2 warps per dst (half row each, float2/lane), 8-deep batched loads.
__global__ void k_gather1(int n) {
    int w    = (blockIdx.x * blockDim.x + threadIdx.x) >> 5;
    int d    = w >> 1;
    if (d >= n) return;
    int half = w & 1;
    int lane = threadIdx.x & 31;
    int foff = half * 32 + lane;            // float2 index within 64-float2 row

    int   cnt = min(g_cnt[d], CAP);
    float dd  = g_dis[d];

    float2 acc = __ldg(&((const float2*)(g_xw1 + (size_t)d * 128))[foff]);

    const int* es = g_esrc + (size_t)d * CAP;
    int i = 0;
    for (; i + 8 <= cnt; i += 8) {
        int s[8];
#pragma unroll
        for (int j = 0; j < 8; j++) s[j] = __ldg(&es[i + j]);
#pragma unroll
        for (int j = 0; j < 8; j++) {
            float2 u = __ldg(&((const float2*)(g_xw1 + (size_t)s[j] * 128))[foff]);
            acc.x += u.x; acc.y += u.y;
        }
    }
    for (; i < cnt; i++) {
        int s = __ldg(&es[i]);
        float2 u = __ldg(&((const float2*)(g_xw1 + (size_t)s * 128))[foff]);
        acc.x += u.x; acc.y += u.y;
    }
    acc.x *= dd; acc.y *= dd;
    __stcs(&((float2*)(g_acc1 + (size_t)d * 128))[foff], acc);
}

// ---- GEMM 2: xw2' = (relu(acc1+b1) @ W2) * dis[row]  [N,128]x[128,64] -----
__global__ void k_gemm2(const float* __restrict__ W2, const float* __restrict__ b1, int n) {
    __shared__ float hs[64 * 128];
    __shared__ float b1s[128];
    int row0 = blockIdx.x * 64;
    int tid  = threadIdx.x;
    if (tid < 128) b1s[tid] = b1[tid];
    __syncthreads();

    const float4* a4  = (const float4*)g_acc1;
    float4*       hs4 = (float4*)hs;
#pragma unroll
    for (int i = 0; i < 8; i++) {
        int idx = tid + i * 256;
        int r   = idx >> 5;
        int k4  = idx & 31;
        int row = row0 + r;
        float4 v = (row < n) ? __ldcs(&a4[(size_t)row * 32 + k4])
                             : make_float4(0.f, 0.f, 0.f, 0.f);
        v.x = fmaxf(v.x + b1s[k4 * 4 + 0], 0.f);
        v.y = fmaxf(v.y + b1s[k4 * 4 + 1], 0.f);
        v.z = fmaxf(v.z + b1s[k4 * 4 + 2], 0.f);
        v.w = fmaxf(v.w + b1s[k4 * 4 + 3], 0.f);
        hs4[idx] = v;
    }
    __syncthreads();

    int colg  = tid & 15;
    int rbase = (tid >> 4) * 4;
    float4 acc[4];
#pragma unroll
    for (int i = 0; i < 4; i++) acc[i] = make_float4(0.f, 0.f, 0.f, 0.f);

    const float4* W4 = (const float4*)W2;
    for (int k = 0; k < 128; k += 2) {
        float4 w0 = __ldg(&W4[k * 16 + colg]);
        float4 w1 = __ldg(&W4[(k + 1) * 16 + colg]);
#pragma unroll
        for (int i = 0; i < 4; i++) {
            float2 a = *(const float2*)&hs[(rbase + i) * 128 + k];   // LDS.64
            acc[i].x += a.x * w0.x + a.y * w1.x;
            acc[i].y += a.x * w0.y + a.y * w1.y;
            acc[i].z += a.x * w0.z + a.y * w1.z;
            acc[i].w += a.x * w0.w + a.y * w1.w;
        }
    }
#pragma unroll
    for (int i = 0; i < 4; i++) {
        int row = row0 + rbase + i;
        if (row < n) {
            float s = g_dis[row];
            float4 v = acc[i];
            v.x *= s; v.y *= s; v.z *= s; v.w *= s;
            ((float4*)g_xw2)[(size_t)row * 16 + colg] = v;
        }
    }
}

// ---- gather 2 + pool: pooled[batch[d]] += relu(dd*(self+sum) + b2) --------
__global__ void k_gather2(const int* __restrict__ batch, const float* __restrict__ b2, int n) {
    int d    = (blockIdx.x * blockDim.x + threadIdx.x) >> 5;
    int lane = threadIdx.x & 31;
    if (d >= n) return;
    int   cnt = min(g_cnt[d], CAP);
    float dd  = g_dis[d];

    float2 acc = __ldg(&((const float2*)(g_xw2 + (size_t)d * 64))[lane]);

    const int* es = g_esrc + (size_t)d * CAP;
    int i = 0;
    for (; i + 8 <= cnt; i += 8) {
        int s[8];
#pragma unroll
        for (int j = 0; j < 8; j++) s[j] = __ldg(&es[i + j]);
#pragma unroll
        for (int j = 0; j < 8; j++) {
            float2 u = __ldg(&((const float2*)(g_xw2 + (size_t)s[j] * 64))[lane]);
            acc.x += u.x; acc.y += u.y;
        }
    }
    for (; i < cnt; i++) {
        int s = __ldg(&es[i]);
        float2 u = __ldg(&((const float2*)(g_xw2 + (size_t)s * 64))[lane]);
        acc.x += u.x; acc.y += u.y;
    }
    float2 b = __ldg(&((const float2*)b2)[lane]);
    float a0 = fmaxf(acc.x * dd + b.x, 0.f);
    float a1 = fmaxf(acc.y * dd + b.y, 0.f);
    int g = __ldg(&batch[d]);
    red_add_v2(&g_pooled[g * 64 + lane * 2], a0, a1);
}

// ---------------- BN statistics: 256 threads = 64 feat x 4 groups ----------
__global__ void k_bnstats() {
    __shared__ float ssum[256], ssq[256];
    int f   = threadIdx.x & 63;
    int grp = threadIdx.x >> 6;
    float s = 0.f, q = 0.f;
    for (int g = grp; g < NUM_GRAPHS; g += 4) {
        float v = g_pooled[g * 64 + f];
        s += v; q += v * v;
    }
    ssum[threadIdx.x] = s; ssq[threadIdx.x] = q;
    __syncthreads();
    if (grp == 0) {
        s = ssum[f] + ssum[f + 64] + ssum[f + 128] + ssum[f + 192];
        q = ssq [f] + ssq [f + 64] + ssq [f + 128] + ssq [f + 192];
        float m   = s * (1.0f / NUM_GRAPHS);
        float var = q * (1.0f / NUM_GRAPHS) - m * m;
        g_mean[f] = m;
        g_rstd[f] = rsqrtf(var + BN_EPS);
    }
}

// ---------------- head: BN affine + MLP; write (out, h) --------------------
__global__ void k_head(const float* __restrict__ gamma, const float* __restrict__ beta,
                       const float* __restrict__ Wo1,   const float* __restrict__ bo1,
                       const float* __restrict__ Wo2,   const float* __restrict__ bo2,
                       float* __restrict__ out) {
    int g = blockIdx.x * blockDim.x + threadIdx.x;
    if (g >= NUM_GRAPHS) return;
    float hid[24];
#pragma unroll
    for (int j = 0; j < 24; j++) hid[j] = __ldg(&bo1[j]);

    float* hout = out + NUM_GRAPHS + (size_t)g * 64;   // h = pooled (stop_gradient)
    for (int f = 0; f < 64; f++) {
        float p = g_pooled[g * 64 + f];
        hout[f] = p;
        float xn = (p - g_mean[f]) * g_rstd[f] * __ldg(&gamma[f]) + __ldg(&beta[f]);
#pragma unroll
        for (int j = 0; j < 24; j++)
            hid[j] += xn * __ldg(&Wo1[f * 24 + j]);
    }
    float o = __ldg(&bo2[0]);
#pragma unroll
    for (int j = 0; j < 24; j++)
        o += fmaxf(hid[j], 0.f) * __ldg(&Wo2[j]);
    out[g] = o;
}

// ---------------- launch ----------------
extern "C" void kernel_launch(void* const* d_in, const int* in_sizes, int n_in,
                              void* d_out, int out_size) {
    const float* x     = (const float*)d_in[0];
    const int*   ei    = (const int*)d_in[1];
    const int*   batch = (const int*)d_in[2];
    const float* W1    = (const float*)d_in[3];
    const float* b1    = (const float*)d_in[4];
    const float* W2    = (const float*)d_in[5];
    const float* b2    = (const float*)d_in[6];
    const float* gamma = (const float*)d_in[7];
    const float* beta  = (const float*)d_in[8];
    const float* Wo1   = (const float*)d_in[9];
    const float* bo1   = (const float*)d_in[10];
    const float* Wo2   = (const float*)d_in[11];
    const float* bo2   = (const float*)d_in[12];

    int N = in_sizes[0] / F1;
    int E = in_sizes[1] / 2;
    const int* src = ei;
    const int* dst = ei + E;
    float* out = (float*)d_out;

    void* cnt_ptr = nullptr;
    void* pooled_ptr = nullptr;
    cudaGetSymbolAddress(&cnt_ptr, g_cnt);
    cudaGetSymbolAddress(&pooled_ptr, g_pooled);
    cudaMemsetAsync(cnt_ptr, 0, NUM_NODES * sizeof(int));
    cudaMemsetAsync(pooled_ptr, 0, NUM_GRAPHS * F2 * sizeof(float));

    k_fill2  <<<(E + 255) / 256, 256>>>(src, dst, E);      // kernel 0
    k_dis    <<<(N + 255) / 256, 256>>>(N);                // kernel 1
    k_gemm1  <<<(N + 63) / 64, 256>>>(x, W1, N);           // kernel 2
    k_gather1<<<(N + 3) / 4, 256>>>(N);                    // kernel 3  <- profiled
    k_gemm2  <<<(N + 63) / 64, 256>>>(W2, b1, N);
    k_gather2<<<(N + 7) / 8, 256>>>(batch, b2, N);
    k_bnstats<<<1, 256>>>();
    k_head<<<(NUM_GRAPHS + 127) / 128, 128>>>(gamma, beta, Wo1, bo1, Wo2, bo2, out);
}

// round 10
// speedup vs baseline: 1.8808x; 1.2268x over previous
#include <cuda_runtime.h>

#define NUM_NODES  100000
#define NUM_GRAPHS 512
#define CAP 96                 // max in-degree slots (Poisson(16) tail: overflow ~1e-20)
#define F1 128
#define F2 64
#define BN_EPS 1e-5f

// ---------------- scratch (static device globals; no allocation) ----------------
__device__ __align__(16) int   g_cnt [NUM_NODES];          // in-degree (excl self)
__device__ __align__(16) int   g_esrc[NUM_NODES * CAP];    // bucket CSR: src ids per dst
__device__ __align__(16) float g_dis [NUM_NODES];
__device__ __align__(16) float g_xw1 [NUM_NODES * F1];     // pre-scaled by dis[row]
__device__ __align__(16) float g_acc1[NUM_NODES * F1];
__device__ __align__(16) float g_xw2 [NUM_NODES * F2];     // pre-scaled by dis[row]
__device__ __align__(16) float g_pooled[NUM_GRAPHS * F2];
__device__ __align__(16) float g_mean[F2];
__device__ __align__(16) float g_rstd[F2];

__device__ __forceinline__ void red_add_v2(float* p, float x, float y) {
    asm volatile("red.global.add.v2.f32 [%0], {%1,%2};"
                 :: "l"(p), "f"(x), "f"(y) : "memory");
}

__device__ __forceinline__ unsigned f2tf(float f) {
    unsigned u;
    asm("cvt.rna.tf32.f32 %0, %1;" : "=r"(u) : "f"(f));
    return u;
}
// split f into tf32 hi + tf32 lo (3xTF32 scheme)
__device__ __forceinline__ void tfsplit(float f, unsigned& hi, unsigned& lo) {
    hi = f2tf(f);
    lo = f2tf(f - __uint_as_float(hi));
}

__device__ __forceinline__ void mma_tf32(float4& c,
    unsigned a0, unsigned a1, unsigned a2, unsigned a3,
    unsigned b0, unsigned b1)
{
    asm volatile(
        "mma.sync.aligned.m16n8k8.row.col.f32.tf32.tf32.f32 "
        "{%0,%1,%2,%3}, {%4,%5,%6,%7}, {%8,%9}, {%0,%1,%2,%3};"
        : "+f"(c.x), "+f"(c.y), "+f"(c.z), "+f"(c.w)
        : "r"(a0), "r"(a1), "r"(a2), "r"(a3), "r"(b0), "r"(b1));
}

// ---------------- fused count + bucket fill ----------------
__global__ void k_fill2(const int* __restrict__ src, const int* __restrict__ dst, int E) {
    int e = blockIdx.x * blockDim.x + threadIdx.x;
    if (e < E) {
        int d = dst[e];
        int slot = atomicAdd(&g_cnt[d], 1);
        if (slot < CAP) g_esrc[(size_t)d * CAP + slot] = src[e];
    }
}

// ---------------- dis = rsqrt(deg+1) ----------------
__global__ void k_dis(int n) {
    int i = blockIdx.x * blockDim.x + threadIdx.x;
    if (i < n) g_dis[i] = rsqrtf((float)(g_cnt[i] + 1));
}

// ---- GEMM 1 (3xTF32 MMA): xw1' = (x @ W1) * dis[row]  [N,128]x[128,128] ----
// 256 threads = 8 warps (4m x 2n). Tile M=64, N=128. K chunked by 16.
__global__ void k_gemm1(const float* __restrict__ x, const float* __restrict__ W, int n) {
    __shared__ float As[64 * 132];      // fp32, padded stride 132
    __shared__ float Ws[16 * 132];      // W chunk fp32, padded
    int tid  = threadIdx.x;
    int lane = tid & 31, warp = tid >> 5;
    int wm = (warp & 3) * 16;           // warp m-base
    int wn = (warp >> 2) * 64;          // warp n-base (0 or 64)
    int row0 = blockIdx.x * 64;
    int gid = lane >> 2, tig = lane & 3;

    const float4* x4 = (const float4*)x;
#pragma unroll
    for (int i = 0; i < 8; i++) {
        int idx = tid + i * 256;        // 0..2047 float4s
        int r = idx >> 5, c4 = idx & 31;
        int row = row0 + r;
        float4 v = (row < n) ? __ldcs(&x4[(size_t)row * 32 + c4])
                             : make_float4(0.f, 0.f, 0.f, 0.f);
        *(float4*)&As[r * 132 + c4 * 4] = v;
    }

    float4 c[8];
#pragma unroll
    for (int t = 0; t < 8; t++) c[t] = make_float4(0.f, 0.f, 0.f, 0.f);

    const float4* W4 = (const float4*)W;
    for (int kc = 0; kc < 8; kc++) {
        __syncthreads();
#pragma unroll
        for (int i = 0; i < 2; i++) {
            int idx = tid + i * 256;    // 16x32 float4s
            int r = idx >> 5, c4 = idx & 31;
            *(float4*)&Ws[r * 132 + c4 * 4] = __ldg(&W4[(size_t)(kc * 16 + r) * 32 + c4]);
        }
        __syncthreads();
#pragma unroll
        for (int ks = 0; ks < 2; ks++) {
            int k0 = kc * 16 + ks * 8;
            int kk = ks * 8;
            unsigned ah[4], al[4];
            tfsplit(As[(wm + gid)     * 132 + k0 + tig],     ah[0], al[0]);
            tfsplit(As[(wm + gid + 8) * 132 + k0 + tig],     ah[1], al[1]);
            tfsplit(As[(wm + gid)     * 132 + k0 + tig + 4], ah[2], al[2]);
            tfsplit(As[(wm + gid + 8) * 132 + k0 + tig + 4], ah[3], al[3]);
#pragma unroll
            for (int t = 0; t < 8; t++) {
                int nn = wn + t * 8 + gid;
                unsigned bh0, bl0, bh1, bl1;
                tfsplit(Ws[(kk + tig)     * 132 + nn], bh0, bl0);
                tfsplit(Ws[(kk + tig + 4) * 132 + nn], bh1, bl1);
                mma_tf32(c[t], al[0], al[1], al[2], al[3], bh0, bh1);  // a_lo*b_hi
                mma_tf32(c[t], ah[0], ah[1], ah[2], ah[3], bl0, bl1);  // a_hi*b_lo
                mma_tf32(c[t], ah[0], ah[1], ah[2], ah[3], bh0, bh1);  // a_hi*b_hi
            }
        }
    }

    int r0 = row0 + wm + gid, r1 = r0 + 8;
    float s0 = (r0 < n) ? g_dis[r0] : 0.f;
    float s1 = (r1 < n) ? g_dis[r1] : 0.f;
#pragma unroll
    for (int t = 0; t < 8; t++) {
        int col = wn + t * 8 + tig * 2;
        if (r0 < n) *(float2*)&g_xw1[(size_t)r0 * 128 + col] = make_float2(c[t].x * s0, c[t].y * s0);
        if (r1 < n) *(float2*)&g_xw1[(size_t)r1 * 128 + col] = make_float2(c[t].z * s1, c[t].w * s1);
    }
}

// ---- gather 1: acc1[d] = dis[d]*(xw1'[d] + sum xw1'[s]) --------
__global__ void k_gather1(int n) {
    int w    = (blockIdx.x * blockDim.x + threadIdx.x) >> 5;
    int d    = w >> 1;
    if (d >= n) return;
    int half = w & 1;
    int lane = threadIdx.x & 31;
    int foff = half * 32 + lane;

    int   cnt = min(g_cnt[d], CAP);
    float dd  = g_dis[d];

    float2 acc = __ldg(&((const float2*)(g_xw1 + (size_t)d * 128))[foff]);

    const int* es = g_esrc + (size_t)d * CAP;
    int i = 0;
    for (; i + 8 <= cnt; i += 8) {
        int s[8];
#pragma unroll
        for (int j = 0; j < 8; j++) s[j] = __ldg(&es[i + j]);
#pragma unroll
        for (int j = 0; j < 8; j++) {
            float2 u = __ldg(&((const float2*)(g_xw1 + (size_t)s[j] * 128))[foff]);
            acc.x += u.x; acc.y += u.y;
        }
    }
    for (; i < cnt; i++) {
        int s = __ldg(&es[i]);
        float2 u = __ldg(&((const float2*)(g_xw1 + (size_t)s * 128))[foff]);
        acc.x += u.x; acc.y += u.y;
    }
    acc.x *= dd; acc.y *= dd;
    __stcs(&((float2*)(g_acc1 + (size_t)d * 128))[foff], acc);
}

// ---- GEMM 2 (3xTF32): xw2' = (relu(acc1+b1) @ W2) * dis  [N,128]x[128,64] --
__global__ void k_gemm2(const float* __restrict__ W2, const float* __restrict__ b1, int n) {
    __shared__ float As[64 * 132];
    __shared__ float Ws[16 * 68];       // W2 chunk 16x64, padded stride 68
    __shared__ float b1s[128];
    int tid  = threadIdx.x;
    int lane = tid & 31, warp = tid >> 5;
    int wm = (warp & 3) * 16;
    int wn = (warp >> 2) * 32;          // 0 or 32
    int row0 = blockIdx.x * 64;
    int gid = lane >> 2, tig = lane & 3;

    if (tid < 128) b1s[tid] = b1[tid];
    __syncthreads();

    const float4* a4 = (const float4*)g_acc1;
#pragma unroll
    for (int i = 0; i < 8; i++) {
        int idx = tid + i * 256;
        int r = idx >> 5, c4 = idx & 31;
        int row = row0 + r;
        float4 v = (row < n) ? __ldcs(&a4[(size_t)row * 32 + c4])
                             : make_float4(0.f, 0.f, 0.f, 0.f);
        v.x = fmaxf(v.x + b1s[c4 * 4 + 0], 0.f);
        v.y = fmaxf(v.y + b1s[c4 * 4 + 1], 0.f);
        v.z = fmaxf(v.z + b1s[c4 * 4 + 2], 0.f);
        v.w = fmaxf(v.w + b1s[c4 * 4 + 3], 0.f);
        *(float4*)&As[r * 132 + c4 * 4] = v;
    }

    float4 c[4];
#pragma unroll
    for (int t = 0; t < 4; t++) c[t] = make_float4(0.f, 0.f, 0.f, 0.f);

    const float4* W4 = (const float4*)W2;
    for (int kc = 0; kc < 8; kc++) {
        __syncthreads();
        {   // 16x64 chunk = 256 float4s, 1 per thread
            int r = tid >> 4, c4 = tid & 15;
            *(float4*)&Ws[r * 68 + c4 * 4] = __ldg(&W4[(size_t)(kc * 16 + r) * 16 + c4]);
        }
        __syncthreads();
#pragma unroll
        for (int ks = 0; ks < 2; ks++) {
            int k0 = kc * 16 + ks * 8;
            int kk = ks * 8;
            unsigned ah[4], al[4];
            tfsplit(As[(wm + gid)     * 132 + k0 + tig],     ah[0], al[0]);
            tfsplit(As[(wm + gid + 8) * 132 + k0 + tig],     ah[1], al[1]);
            tfsplit(As[(wm + gid)     * 132 + k0 + tig + 4], ah[2], al[2]);
            tfsplit(As[(wm + gid + 8) * 132 + k0 + tig + 4], ah[3], al[3]);
#pragma unroll
            for (int t = 0; t < 4; t++) {
                int nn = wn + t * 8 + gid;
                unsigned bh0, bl0, bh1, bl1;
                tfsplit(Ws[(kk + tig)     * 68 + nn], bh0, bl0);
                tfsplit(Ws[(kk + tig + 4) * 68 + nn], bh1, bl1);
                mma_tf32(c[t], al[0], al[1], al[2], al[3], bh0, bh1);
                mma_tf32(c[t], ah[0], ah[1], ah[2], ah[3], bl0, bl1);
                mma_tf32(c[t], ah[0], ah[1], ah[2], ah[3], bh0, bh1);
            }
        }
    }

    int r0 = row0 + wm + gid, r1 = r0 + 8;
    float s0 = (r0 < n) ? g_dis[r0] : 0.f;
    float s1 = (r1 < n) ? g_dis[r1] : 0.f;
#pragma unroll
    for (int t = 0; t < 4; t++) {
        int col = wn + t * 8 + tig * 2;
        if (r0 < n) *(float2*)&g_xw2[(size_t)r0 * 64 + col] = make_float2(c[t].x * s0, c[t].y * s0);
        if (r1 < n) *(float2*)&g_xw2[(size_t)r1 * 64 + col] = make_float2(c[t].z * s1, c[t].w * s1);
    }
}

// ---- gather 2 + pool: pooled[batch[d]] += relu(dd*(self+sum) + b2) --------
__global__ void k_gather2(const int* __restrict__ batch, const float* __restrict__ b2, int n) {
    int d    = (blockIdx.x * blockDim.x + threadIdx.x) >> 5;
    int lane = threadIdx.x & 31;
    if (d >= n) return;
    int   cnt = min(g_cnt[d], CAP);
    float dd  = g_dis[d];

    float2 acc = __ldg(&((const float2*)(g_xw2 + (size_t)d * 64))[lane]);

    const int* es = g_esrc + (size_t)d * CAP;
    int i = 0;
    for (; i + 8 <= cnt; i += 8) {
        int s[8];
#pragma unroll
        for (int j = 0; j < 8; j++) s[j] = __ldg(&es[i + j]);
#pragma unroll
        for (int j = 0; j < 8; j++) {
            float2 u = __ldg(&((const float2*)(g_xw2 + (size_t)s[j] * 64))[lane]);
            acc.x += u.x; acc.y += u.y;
        }
    }
    for (; i < cnt; i++) {
        int s = __ldg(&es[i]);
        float2 u = __ldg(&((const float2*)(g_xw2 + (size_t)s * 64))[lane]);
        acc.x += u.x; acc.y += u.y;
    }
    float2 b = __ldg(&((const float2*)b2)[lane]);
    float a0 = fmaxf(acc.x * dd + b.x, 0.f);
    float a1 = fmaxf(acc.y * dd + b.y, 0.f);
    int g = __ldg(&batch[d]);
    red_add_v2(&g_pooled[g * 64 + lane * 2], a0, a1);
}

// ---------------- BN statistics: 256 threads = 64 feat x 4 groups ----------
__global__ void k_bnstats() {
    __shared__ float ssum[256], ssq[256];
    int f   = threadIdx.x & 63;
    int grp = threadIdx.x >> 6;
    float s = 0.f, q = 0.f;
    for (int g = grp; g < NUM_GRAPHS; g += 4) {
        float v = g_pooled[g * 64 + f];
        s += v; q += v * v;
    }
    ssum[threadIdx.x] = s; ssq[threadIdx.x] = q;
    __syncthreads();
    if (grp == 0) {
        s = ssum[f] + ssum[f + 64] + ssum[f + 128] + ssum[f + 192];
        q = ssq [f] + ssq [f + 64] + ssq [f + 128] + ssq [f + 192];
        float m   = s * (1.0f / NUM_GRAPHS);
        float var = q * (1.0f / NUM_GRAPHS) - m * m;
        g_mean[f] = m;
        g_rstd[f] = rsqrtf(var + BN_EPS);
    }
}

// ---------------- head: BN affine + MLP; write (out, h) --------------------
__global__ void k_head(const float* __restrict__ gamma, const float* __restrict__ beta,
                       const float* __restrict__ Wo1,   const float* __restrict__ bo1,
                       const float* __restrict__ Wo2,   const float* __restrict__ bo2,
                       float* __restrict__ out) {
    int g = blockIdx.x * blockDim.x + threadIdx.x;
    if (g >= NUM_GRAPHS) return;
    float hid[24];
#pragma unroll
    for (int j = 0; j < 24; j++) hid[j] = __ldg(&bo1[j]);

    float* hout = out + NUM_GRAPHS + (size_t)g * 64;   // h = pooled (stop_gradient)
    for (int f = 0; f < 64; f++) {
        float p = g_pooled[g * 64 + f];
        hout[f] = p;
        float xn = (p - g_mean[f]) * g_rstd[f] * __ldg(&gamma[f]) + __ldg(&beta[f]);
#pragma unroll
        for (int j = 0; j < 24; j++)
            hid[j] += xn * __ldg(&Wo1[f * 24 + j]);
    }
    float o = __ldg(&bo2[0]);
#pragma unroll
    for (int j = 0; j < 24; j++)
        o += fmaxf(hid[j], 0.f) * __ldg(&Wo2[j]);
    out[g] = o;
}

// ---------------- launch ----------------
extern "C" void kernel_launch(void* const* d_in, const int* in_sizes, int n_in,
                              void* d_out, int out_size) {
    const float* x     = (const float*)d_in[0];
    const int*   ei    = (const int*)d_in[1];
    const int*   batch = (const int*)d_in[2];
    const float* W1    = (const float*)d_in[3];
    const float* b1    = (const float*)d_in[4];
    const float* W2    = (const float*)d_in[5];
    const float* b2    = (const float*)d_in[6];
    const float* gamma = (const float*)d_in[7];
    const float* beta  = (const float*)d_in[8];
    const float* Wo1   = (const float*)d_in[9];
    const float* bo1   = (const float*)d_in[10];
    const float* Wo2   = (const float*)d_in[11];
    const float* bo2   = (const float*)d_in[12];

    int N = in_sizes[0] / F1;
    int E = in_sizes[1] / 2;
    const int* src = ei;
    const int* dst = ei + E;
    float* out = (float*)d_out;

    void* cnt_ptr = nullptr;
    void* pooled_ptr = nullptr;
    cudaGetSymbolAddress(&cnt_ptr, g_cnt);
    cudaGetSymbolAddress(&pooled_ptr, g_pooled);
    cudaMemsetAsync(cnt_ptr, 0, NUM_NODES * sizeof(int));
    cudaMemsetAsync(pooled_ptr, 0, NUM_GRAPHS * F2 * sizeof(float));

    k_fill2  <<<(E + 255) / 256, 256>>>(src, dst, E);
    k_dis    <<<(N + 255) / 256, 256>>>(N);
    k_gemm1  <<<(N + 63) / 64, 256>>>(x, W1, N);
    k_gather1<<<(N + 3) / 4, 256>>>(N);
    k_gemm2  <<<(N + 63) / 64, 256>>>(W2, b1, N);
    k_gather2<<<(N + 7) / 8, 256>>>(batch, b2, N);
    k_bnstats<<<1, 256>>>();
    k_head<<<(NUM_GRAPHS + 127) / 128, 128>>>(gamma, beta, Wo1, bo1, Wo2, bo2, out);
}